// round 7
// baseline (speedup 1.0000x reference)
#include <cuda_runtime.h>
#include <cuda_bf16.h>
#include <cstdint>

// Problem constants
#define BATCH 4
#define SEQ   2048
#define DMODEL 1024
#define NHEADS 16
#define HD    64
#define ROWS  (BATCH * SEQ)          // 8192
#define QKV_N (3 * DMODEL)           // 3072

// Scratch (allocation-free rule: __device__ globals)
__device__ float g_qkv[(size_t)ROWS * QKV_N];
__device__ __nv_bfloat16 g_xh[(size_t)ROWS * DMODEL];
__device__ __nv_bfloat16 g_xl[(size_t)ROWS * DMODEL];
__device__ __nv_bfloat16 g_wqh[(size_t)QKV_N * DMODEL];
__device__ __nv_bfloat16 g_wql[(size_t)QKV_N * DMODEL];
__device__ __nv_bfloat16 g_woh[(size_t)DMODEL * DMODEL];
__device__ __nv_bfloat16 g_wol[(size_t)DMODEL * DMODEL];
__device__ __nv_bfloat16 g_ath[(size_t)ROWS * DMODEL];
__device__ __nv_bfloat16 g_atl[(size_t)ROWS * DMODEL];

// ---------------------------------------------------------------------------
// helpers
// ---------------------------------------------------------------------------
__device__ __forceinline__ uint32_t s2u(const void* p) {
    uint32_t a;
    asm("{ .reg .u64 t; cvta.to.shared.u64 t, %1; cvt.u32.u64 %0, t; }"
        : "=r"(a) : "l"(p));
    return a;
}
__device__ __forceinline__ uint32_t tf32u(float x) {
    uint32_t u; asm("cvt.rn.tf32.f32 %0, %1;" : "=r"(u) : "f"(x)); return u;
}
__device__ __forceinline__ float tf32f(float x) { return __uint_as_float(tf32u(x)); }

__device__ __forceinline__ void mma_tf32(float& d0, float& d1, float& d2, float& d3,
                                         uint32_t a0, uint32_t a1, uint32_t a2, uint32_t a3,
                                         uint32_t b0, uint32_t b1)
{
    asm volatile(
        "mma.sync.aligned.m16n8k8.row.col.f32.tf32.tf32.f32 "
        "{%0,%1,%2,%3}, {%4,%5,%6,%7}, {%8,%9}, {%0,%1,%2,%3};"
        : "+f"(d0), "+f"(d1), "+f"(d2), "+f"(d3)
        : "r"(a0), "r"(a1), "r"(a2), "r"(a3), "r"(b0), "r"(b1));
}

__device__ __forceinline__ void mma_bf16(float& d0, float& d1, float& d2, float& d3,
                                         uint32_t a0, uint32_t a1, uint32_t a2, uint32_t a3,
                                         uint32_t b0, uint32_t b1)
{
    asm volatile(
        "mma.sync.aligned.m16n8k16.row.col.f32.bf16.bf16.f32 "
        "{%0,%1,%2,%3}, {%4,%5,%6,%7}, {%8,%9}, {%0,%1,%2,%3};"
        : "+f"(d0), "+f"(d1), "+f"(d2), "+f"(d3)
        : "r"(a0), "r"(a1), "r"(a2), "r"(a3), "r"(b0), "r"(b1));
}

__device__ __forceinline__ void ldmx4(uint32_t* r, uint32_t addr) {
    asm volatile("ldmatrix.sync.aligned.m8n8.x4.shared.b16 {%0,%1,%2,%3}, [%4];"
                 : "=r"(r[0]), "=r"(r[1]), "=r"(r[2]), "=r"(r[3]) : "r"(addr));
}

__device__ __forceinline__ void cpasync16(uint32_t dst, const void* src) {
    asm volatile("cp.async.cg.shared.global [%0], [%1], 16;" :: "r"(dst), "l"(src));
}
#define CP_COMMIT() asm volatile("cp.async.commit_group;" ::: "memory")
#define CP_WAIT0()  asm volatile("cp.async.wait_group 0;" ::: "memory")
#define CP_WAIT1()  asm volatile("cp.async.wait_group 1;" ::: "memory")

// ---------------------------------------------------------------------------
// split kernels: fp32 -> bf16 hi + lo
// ---------------------------------------------------------------------------
__global__ void split_kernel(const float* __restrict__ in,
                             __nv_bfloat16* __restrict__ hi,
                             __nv_bfloat16* __restrict__ lo, int n4)
{
    int i = blockIdx.x * blockDim.x + threadIdx.x;
    if (i >= n4) return;
    float4 v = *(const float4*)(in + (size_t)i * 4);
    __nv_bfloat16 hx = __float2bfloat16(v.x), hy = __float2bfloat16(v.y);
    __nv_bfloat16 hz = __float2bfloat16(v.z), hw = __float2bfloat16(v.w);
    __nv_bfloat162 h01{hx, hy}, h23{hz, hw};
    __nv_bfloat162 l01{__float2bfloat16(v.x - __bfloat162float(hx)),
                       __float2bfloat16(v.y - __bfloat162float(hy))};
    __nv_bfloat162 l23{__float2bfloat16(v.z - __bfloat162float(hz)),
                       __float2bfloat16(v.w - __bfloat162float(hw))};
    *(__nv_bfloat162*)(hi + (size_t)i * 4)     = h01;
    *(__nv_bfloat162*)(hi + (size_t)i * 4 + 2) = h23;
    *(__nv_bfloat162*)(lo + (size_t)i * 4)     = l01;
    *(__nv_bfloat162*)(lo + (size_t)i * 4 + 2) = l23;
}

// transpose + split: in[K][N] fp32 -> hi/lo [N][K] bf16
__global__ void split_tr_kernel(const float* __restrict__ in,
                                __nv_bfloat16* __restrict__ hi,
                                __nv_bfloat16* __restrict__ lo, int K, int N)
{
    __shared__ float t[32][33];
    const int n0 = blockIdx.x * 32, k0 = blockIdx.y * 32;
    const int tx = threadIdx.x, ty = threadIdx.y;
    #pragma unroll
    for (int r = 0; r < 4; r++)
        t[ty + 8 * r][tx] = in[(size_t)(k0 + ty + 8 * r) * N + n0 + tx];
    __syncthreads();
    #pragma unroll
    for (int r = 0; r < 4; r++) {
        float v = t[tx][ty + 8 * r];
        __nv_bfloat16 h = __float2bfloat16(v);
        size_t o = (size_t)(n0 + ty + 8 * r) * K + k0 + tx;
        hi[o] = h;
        lo[o] = __float2bfloat16(v - __bfloat162float(h));
    }
}

// ---------------------------------------------------------------------------
// bf16 3-split GEMM via mma.m16n8k16 + ldmatrix.x4.
// C[M,N] = (Ah+Al)[M,K] @ (Bh+Bl)[N,K]^T (+bias), fp32 accum.
// 128x128 block tile, BK=32, 2-stage cp.async pipeline, 8 warps (2x4 grid),
// warp tile 64x32. smem rows padded to 40 bf16 (80B) -> conflict-free ldmatrix.
// ---------------------------------------------------------------------------
#define RST   40                         // smem row stride in bf16 (80 B)
#define ARR_B (128 * RST * 2)            // 10240 B per array
#define STG_B (4 * ARR_B)                // 40960 B per stage (Ah|Al|Bh|Bl)
#define GEMM2_SMEM (2 * STG_B)           // 81920 B

__global__ void __launch_bounds__(256, 2) gemm_bf16_kernel(
    const __nv_bfloat16* __restrict__ Ah, const __nv_bfloat16* __restrict__ Al,
    const __nv_bfloat16* __restrict__ Bh, const __nv_bfloat16* __restrict__ Bl,
    const float* __restrict__ bias, float* __restrict__ C,
    int M, int N, int K)
{
    extern __shared__ char smem2[];
    const uint32_t sb = s2u(smem2);

    const int tid  = threadIdx.x;
    const int lane = tid & 31;
    const int warp = tid >> 5;
    const int m0 = blockIdx.y * 128;
    const int n0 = blockIdx.x * 128;

    const int wrow = warp >> 2;        // 0..1
    const int wcol = warp & 3;         // 0..3
    const int mbase = wrow * 64;
    const int nbase = wcol * 32;
    const int r = lane >> 2;           // 0..7
    const int c = lane & 3;            // 0..3
    const int lr = lane & 15;          // ldmatrix row select
    const int lc = lane >> 4;          // ldmatrix k-chunk select

    const __nv_bfloat16* srcs[4] = {
        Ah + (size_t)m0 * K, Al + (size_t)m0 * K,
        Bh + (size_t)n0 * K, Bl + (size_t)n0 * K };

    float acc[4][4][4];
    #pragma unroll
    for (int i = 0; i < 4; i++)
        #pragma unroll
        for (int j = 0; j < 4; j++)
            #pragma unroll
            for (int t = 0; t < 4; t++) acc[i][j][t] = 0.f;

    // one chunk = 32 k-cols of all four arrays (16 KB). 8 cp.async per thread.
    auto load_chunk = [&](int kc, int buf) {
        const uint32_t bb = sb + buf * STG_B;
        #pragma unroll
        for (int u = 0; u < 8; u++) {
            const int arr = u >> 1;                 // compile-time per unroll
            const int w = (u & 1) * 256 + tid;      // 0..511
            const int row = w >> 2, j = w & 3;
            cpasync16(bb + arr * ARR_B + row * (RST * 2) + j * 16,
                      srcs[arr] + (size_t)row * K + kc * 32 + j * 8);
        }
        CP_COMMIT();
    };

    const int NCH = K / 32;
    load_chunk(0, 0);
    load_chunk(1, 1);

    for (int i = 0; i < NCH; i++) {
        const int buf = i & 1;
        if (i + 1 < NCH) { CP_WAIT1(); } else { CP_WAIT0(); }
        __syncthreads();

        const uint32_t bb = sb + buf * STG_B;
        const uint32_t baseAh = bb;
        const uint32_t baseAl = bb + ARR_B;
        const uint32_t baseBh = bb + 2 * ARR_B;
        const uint32_t baseBl = bb + 3 * ARR_B;

        #pragma unroll
        for (int ks = 0; ks < 2; ks++) {
            const uint32_t ko = ks * 32;    // k16 chunk byte offset
            uint32_t ah[4][4], al[4][4], bh[2][4], bl[2][4];
            #pragma unroll
            for (int mt = 0; mt < 4; mt++) {
                const uint32_t ro = (uint32_t)(mbase + mt * 16 + lr) * (RST * 2) + ko + lc * 16;
                ldmx4(ah[mt], baseAh + ro);
                ldmx4(al[mt], baseAl + ro);
            }
            #pragma unroll
            for (int p = 0; p < 2; p++) {
                const uint32_t ro = (uint32_t)(nbase + p * 16 + lr) * (RST * 2) + ko + lc * 16;
                ldmx4(bh[p], baseBh + ro);
                ldmx4(bl[p], baseBl + ro);
            }
            #pragma unroll
            for (int mt = 0; mt < 4; mt++)
                #pragma unroll
                for (int nt = 0; nt < 4; nt++) {
                    const int p = nt >> 1, q = nt & 1;
                    mma_bf16(acc[mt][nt][0], acc[mt][nt][1], acc[mt][nt][2], acc[mt][nt][3],
                             ah[mt][0], ah[mt][1], ah[mt][2], ah[mt][3],
                             bh[p][q], bh[p][q + 2]);
                    mma_bf16(acc[mt][nt][0], acc[mt][nt][1], acc[mt][nt][2], acc[mt][nt][3],
                             ah[mt][0], ah[mt][1], ah[mt][2], ah[mt][3],
                             bl[p][q], bl[p][q + 2]);
                    mma_bf16(acc[mt][nt][0], acc[mt][nt][1], acc[mt][nt][2], acc[mt][nt][3],
                             al[mt][0], al[mt][1], al[mt][2], al[mt][3],
                             bh[p][q], bh[p][q + 2]);
                }
        }
        __syncthreads();
        if (i + 2 < NCH) load_chunk(i + 2, buf);
    }

    // epilogue: c0,c1 -> (row, 2c..2c+1); c2,c3 -> (row+8, ...)
    #pragma unroll
    for (int mt = 0; mt < 4; mt++) {
        const int row0 = m0 + mbase + mt * 16 + r;
        #pragma unroll
        for (int nt = 0; nt < 4; nt++) {
            const int col = n0 + nbase + nt * 8 + 2 * c;
            float2 v0 = make_float2(acc[mt][nt][0], acc[mt][nt][1]);
            float2 v1 = make_float2(acc[mt][nt][2], acc[mt][nt][3]);
            if (bias) {
                float2 bb = *(const float2*)(bias + col);
                v0.x += bb.x; v0.y += bb.y;
                v1.x += bb.x; v1.y += bb.y;
            }
            *(float2*)(C + (size_t)row0 * N + col)       = v0;
            *(float2*)(C + (size_t)(row0 + 8) * N + col) = v1;
        }
    }
}

// ---------------------------------------------------------------------------
// Flash attention v2 (tf32 mma), causal — round-6 winner; epilogue now emits
// bf16 hi/lo so the out-projection consumes it directly.
// ---------------------------------------------------------------------------
#define FBM 128
#define FBN 64
#define QST 68
#define KST 68
#define VST 72
#define FLASH_SMEM ((2*FBM*QST + FBN*KST + FBN*VST) * 4)   // 105472 B

__global__ void __launch_bounds__(256, 2) flash_tc_kernel(
    const float* __restrict__ qkv,
    __nv_bfloat16* __restrict__ outh, __nv_bfloat16* __restrict__ outl)
{
    extern __shared__ float sm[];
    float* Qh = sm;
    float* Ql = Qh + FBM * QST;
    float* Ks = Ql + FBM * QST;
    float* Vs = Ks + FBN * KST;

    const int tid  = threadIdx.x;
    const int lane = tid & 31;
    const int warp = tid >> 5;
    const int qt = (int)gridDim.x - 1 - (int)blockIdx.x;
    const int bh = blockIdx.y;
    const int b  = bh >> 4;
    const int h  = bh & 15;

    const size_t rs = (size_t)QKV_N;
    const float* qb = qkv + (size_t)b * SEQ * rs + h * HD;
    const float* kb = qb + DMODEL;
    const int q0 = qt * FBM;

    for (int idx = tid; idx < FBM * 16; idx += 256) {
        int rr = idx >> 4, c4 = (idx & 15) * 4;
        float4 q = *(const float4*)(qb + (size_t)(q0 + rr) * rs + c4);
        float hx = tf32f(q.x), hy = tf32f(q.y), hz = tf32f(q.z), hw = tf32f(q.w);
        *(float4*)&Qh[rr * QST + c4] = make_float4(hx, hy, hz, hw);
        *(float4*)&Ql[rr * QST + c4] = make_float4(tf32f(q.x - hx), tf32f(q.y - hy),
                                                   tf32f(q.z - hz), tf32f(q.w - hw));
    }

    const int r = lane >> 2;
    const int c = lane & 3;
    const int m0 = warp * 16;

    float o[8][4];
    #pragma unroll
    for (int nt = 0; nt < 8; nt++)
        #pragma unroll
        for (int t = 0; t < 4; t++) o[nt][t] = 0.f;
    float mx0 = -1e30f, mx1 = -1e30f, l0 = 0.f, l1 = 0.f;
    const float sl2e = 0.125f * 1.4426950408889634f;

    const int nkt = 2 * qt + 2;
    for (int kt = 0; kt < nkt; kt++) {
        __syncthreads();

        for (int idx = tid; idx < FBN * 16; idx += 256) {
            int rr = idx >> 4, ch = (idx & 15) * 4;
            const float* src = kb + (size_t)(kt * FBN + rr) * rs + ch;
            cpasync16(s2u(&Ks[rr * KST + ch]), src);
            cpasync16(s2u(&Vs[rr * VST + ch]), src + DMODEL);
        }
        CP_COMMIT();
        CP_WAIT0();
        __syncthreads();

        float s[8][4];
        #pragma unroll
        for (int nt = 0; nt < 8; nt++)
            #pragma unroll
            for (int t = 0; t < 4; t++) s[nt][t] = 0.f;

        #pragma unroll
        for (int kc = 0; kc < 8; kc++) {
            const int k8 = kc * 8;
            uint32_t ah0 = __float_as_uint(Qh[(m0 + r) * QST + k8 + c]);
            uint32_t ah1 = __float_as_uint(Qh[(m0 + r + 8) * QST + k8 + c]);
            uint32_t ah2 = __float_as_uint(Qh[(m0 + r) * QST + k8 + c + 4]);
            uint32_t ah3 = __float_as_uint(Qh[(m0 + r + 8) * QST + k8 + c + 4]);
            uint32_t al0 = __float_as_uint(Ql[(m0 + r) * QST + k8 + c]);
            uint32_t al1 = __float_as_uint(Ql[(m0 + r + 8) * QST + k8 + c]);
            uint32_t al2 = __float_as_uint(Ql[(m0 + r) * QST + k8 + c + 4]);
            uint32_t al3 = __float_as_uint(Ql[(m0 + r + 8) * QST + k8 + c + 4]);
            #pragma unroll
            for (int nt = 0; nt < 8; nt++) {
                uint32_t b0 = tf32u(Ks[(nt * 8 + r) * KST + k8 + c]);
                uint32_t b1 = tf32u(Ks[(nt * 8 + r) * KST + k8 + c + 4]);
                mma_tf32(s[nt][0], s[nt][1], s[nt][2], s[nt][3], ah0, ah1, ah2, ah3, b0, b1);
                mma_tf32(s[nt][0], s[nt][1], s[nt][2], s[nt][3], al0, al1, al2, al3, b0, b1);
            }
        }

        if (kt >= 2 * qt) {
            const int q0i = q0 + m0 + r;
            #pragma unroll
            for (int nt = 0; nt < 8; nt++) {
                int k0i = kt * FBN + nt * 8 + 2 * c;
                if (k0i     > q0i)     s[nt][0] = -1e30f;
                if (k0i + 1 > q0i)     s[nt][1] = -1e30f;
                if (k0i     > q0i + 8) s[nt][2] = -1e30f;
                if (k0i + 1 > q0i + 8) s[nt][3] = -1e30f;
            }
        }

        {
            float t = -1e30f;
            #pragma unroll
            for (int nt = 0; nt < 8; nt++) t = fmaxf(t, fmaxf(s[nt][0], s[nt][1]));
            t = fmaxf(t, __shfl_xor_sync(0xffffffffu, t, 1));
            t = fmaxf(t, __shfl_xor_sync(0xffffffffu, t, 2));
            t *= sl2e;
            float mn = fmaxf(mx0, t);
            float alpha = exp2f(mx0 - mn);
            float ps = 0.f;
            #pragma unroll
            for (int nt = 0; nt < 8; nt++) {
                float p0 = exp2f(s[nt][0] * sl2e - mn);
                float p1 = exp2f(s[nt][1] * sl2e - mn);
                s[nt][0] = p0; s[nt][1] = p1; ps += p0 + p1;
            }
            ps += __shfl_xor_sync(0xffffffffu, ps, 1);
            ps += __shfl_xor_sync(0xffffffffu, ps, 2);
            l0 = l0 * alpha + ps; mx0 = mn;
            #pragma unroll
            for (int nt = 0; nt < 8; nt++) { o[nt][0] *= alpha; o[nt][1] *= alpha; }
        }
        {
            float t = -1e30f;
            #pragma unroll
            for (int nt = 0; nt < 8; nt++) t = fmaxf(t, fmaxf(s[nt][2], s[nt][3]));
            t = fmaxf(t, __shfl_xor_sync(0xffffffffu, t, 1));
            t = fmaxf(t, __shfl_xor_sync(0xffffffffu, t, 2));
            t *= sl2e;
            float mn = fmaxf(mx1, t);
            float alpha = exp2f(mx1 - mn);
            float ps = 0.f;
            #pragma unroll
            for (int nt = 0; nt < 8; nt++) {
                float p0 = exp2f(s[nt][2] * sl2e - mn);
                float p1 = exp2f(s[nt][3] * sl2e - mn);
                s[nt][2] = p0; s[nt][3] = p1; ps += p0 + p1;
            }
            ps += __shfl_xor_sync(0xffffffffu, ps, 1);
            ps += __shfl_xor_sync(0xffffffffu, ps, 2);
            l1 = l1 * alpha + ps; mx1 = mn;
            #pragma unroll
            for (int nt = 0; nt < 8; nt++) { o[nt][2] *= alpha; o[nt][3] *= alpha; }
        }

        {
            const int src0 = 4 * r + (c >> 1);
            const int src1 = src0 + 2;
            const bool odd = (c & 1);
            #pragma unroll
            for (int kc = 0; kc < 8; kc++) {
                const int k8 = kc * 8;
                float t00 = __shfl_sync(0xffffffffu, s[kc][0], src0);
                float t01 = __shfl_sync(0xffffffffu, s[kc][1], src0);
                float t02 = __shfl_sync(0xffffffffu, s[kc][2], src0);
                float t03 = __shfl_sync(0xffffffffu, s[kc][3], src0);
                float t10 = __shfl_sync(0xffffffffu, s[kc][0], src1);
                float t11 = __shfl_sync(0xffffffffu, s[kc][1], src1);
                float t12 = __shfl_sync(0xffffffffu, s[kc][2], src1);
                float t13 = __shfl_sync(0xffffffffu, s[kc][3], src1);
                uint32_t a0 = tf32u(odd ? t01 : t00);
                uint32_t a1 = tf32u(odd ? t03 : t02);
                uint32_t a2 = tf32u(odd ? t11 : t10);
                uint32_t a3 = tf32u(odd ? t13 : t12);
                #pragma unroll
                for (int nt = 0; nt < 8; nt++) {
                    uint32_t b0 = tf32u(Vs[(k8 + c) * VST + nt * 8 + r]);
                    uint32_t b1 = tf32u(Vs[(k8 + c + 4) * VST + nt * 8 + r]);
                    mma_tf32(o[nt][0], o[nt][1], o[nt][2], o[nt][3], a0, a1, a2, a3, b0, b1);
                }
            }
        }
    }

    // epilogue: normalize and write bf16 hi/lo att
    const float inv0 = 1.f / l0;
    const float inv1 = 1.f / l1;
    const size_t row0 = (size_t)(b * SEQ + q0 + m0 + r) * DMODEL + h * HD;
    const size_t row1 = row0 + (size_t)8 * DMODEL;
    #pragma unroll
    for (int nt = 0; nt < 8; nt++) {
        const int col = nt * 8 + 2 * c;
        float v0 = o[nt][0] * inv0, v1 = o[nt][1] * inv0;
        float v2 = o[nt][2] * inv1, v3 = o[nt][3] * inv1;
        __nv_bfloat16 h0 = __float2bfloat16(v0), h1 = __float2bfloat16(v1);
        __nv_bfloat16 h2 = __float2bfloat16(v2), h3 = __float2bfloat16(v3);
        *(__nv_bfloat162*)(outh + row0 + col) = __nv_bfloat162{h0, h1};
        *(__nv_bfloat162*)(outh + row1 + col) = __nv_bfloat162{h2, h3};
        *(__nv_bfloat162*)(outl + row0 + col) =
            __nv_bfloat162{__float2bfloat16(v0 - __bfloat162float(h0)),
                           __float2bfloat16(v1 - __bfloat162float(h1))};
        *(__nv_bfloat162*)(outl + row1 + col) =
            __nv_bfloat162{__float2bfloat16(v2 - __bfloat162float(h2)),
                           __float2bfloat16(v3 - __bfloat162float(h3))};
    }
}

// ---------------------------------------------------------------------------
extern "C" void kernel_launch(void* const* d_in, const int* in_sizes, int n_in,
                              void* d_out, int out_size)
{
    const float* x     = (const float*)d_in[0];
    const float* w_qkv = (const float*)d_in[1];
    const float* w_out = (const float*)d_in[2];
    const float* b_out = (const float*)d_in[3];
    float* out = (float*)d_out;

    float* qkv;
    __nv_bfloat16 *xh, *xl, *wqh, *wql, *woh, *wol, *ath, *atl;
    cudaGetSymbolAddress((void**)&qkv, g_qkv);
    cudaGetSymbolAddress((void**)&xh, g_xh);   cudaGetSymbolAddress((void**)&xl, g_xl);
    cudaGetSymbolAddress((void**)&wqh, g_wqh); cudaGetSymbolAddress((void**)&wql, g_wql);
    cudaGetSymbolAddress((void**)&woh, g_woh); cudaGetSymbolAddress((void**)&wol, g_wol);
    cudaGetSymbolAddress((void**)&ath, g_ath); cudaGetSymbolAddress((void**)&atl, g_atl);

    // 0) splits: x -> bf16 hi/lo; weights -> transposed bf16 hi/lo
    {
        int n4 = ROWS * DMODEL / 4;
        split_kernel<<<(n4 + 255) / 256, 256>>>(x, xh, xl, n4);
        split_tr_kernel<<<dim3(QKV_N / 32, DMODEL / 32), dim3(32, 8)>>>(w_qkv, wqh, wql, DMODEL, QKV_N);
        split_tr_kernel<<<dim3(DMODEL / 32, DMODEL / 32), dim3(32, 8)>>>(w_out, woh, wol, DMODEL, DMODEL);
    }

    cudaFuncSetAttribute(gemm_bf16_kernel,
                         cudaFuncAttributeMaxDynamicSharedMemorySize, GEMM2_SMEM);

    // 1) QKV projection (bf16 3-split mma + ldmatrix)
    {
        dim3 grid(QKV_N / 128, ROWS / 128);
        gemm_bf16_kernel<<<grid, 256, GEMM2_SMEM>>>(xh, xl, wqh, wql, nullptr, qkv,
                                                    ROWS, QKV_N, DMODEL);
    }

    // 2) Flash attention (tf32 mma, 2 CTAs/SM)
    {
        cudaFuncSetAttribute(flash_tc_kernel,
                             cudaFuncAttributeMaxDynamicSharedMemorySize, FLASH_SMEM);
        dim3 grid(SEQ / FBM, BATCH * NHEADS);
        flash_tc_kernel<<<grid, 256, FLASH_SMEM>>>(qkv, ath, atl);
    }

    // 3) Output projection + bias (bf16 3-split)
    {
        dim3 grid(DMODEL / 128, ROWS / 128);
        gemm_bf16_kernel<<<grid, 256, GEMM2_SMEM>>>(ath, atl, woh, wol, b_out, out,
                                                    ROWS, DMODEL, DMODEL);
    }
}

// round 8
// speedup vs baseline: 1.0299x; 1.0299x over previous
#include <cuda_runtime.h>
#include <cuda_bf16.h>
#include <cstdint>

// Problem constants
#define BATCH 4
#define SEQ   2048
#define DMODEL 1024
#define NHEADS 16
#define HD    64
#define ROWS  (BATCH * SEQ)          // 8192
#define QKV_N (3 * DMODEL)           // 3072

// Scratch (allocation-free rule: __device__ globals)
__device__ float g_qkv[(size_t)ROWS * QKV_N];
__device__ float g_att[(size_t)ROWS * DMODEL];

// ---------------------------------------------------------------------------
// helpers
// ---------------------------------------------------------------------------
__device__ __forceinline__ uint32_t s2u(const void* p) {
    uint32_t a;
    asm("{ .reg .u64 t; cvta.to.shared.u64 t, %1; cvt.u32.u64 %0, t; }"
        : "=r"(a) : "l"(p));
    return a;
}
__device__ __forceinline__ uint32_t tf32u(float x) {
    uint32_t u; asm("cvt.rn.tf32.f32 %0, %1;" : "=r"(u) : "f"(x)); return u;
}
__device__ __forceinline__ float tf32f(float x) { return __uint_as_float(tf32u(x)); }

__device__ __forceinline__ void mma_tf32(float& d0, float& d1, float& d2, float& d3,
                                         uint32_t a0, uint32_t a1, uint32_t a2, uint32_t a3,
                                         uint32_t b0, uint32_t b1)
{
    asm volatile(
        "mma.sync.aligned.m16n8k8.row.col.f32.tf32.tf32.f32 "
        "{%0,%1,%2,%3}, {%4,%5,%6,%7}, {%8,%9}, {%0,%1,%2,%3};"
        : "+f"(d0), "+f"(d1), "+f"(d2), "+f"(d3)
        : "r"(a0), "r"(a1), "r"(a2), "r"(a3), "r"(b0), "r"(b1));
}

__device__ __forceinline__ void cpasync16(uint32_t dst, const void* src) {
    asm volatile("cp.async.cg.shared.global [%0], [%1], 16;" :: "r"(dst), "l"(src));
}
#define CP_COMMIT() asm volatile("cp.async.commit_group;" ::: "memory")
#define CP_WAIT0()  asm volatile("cp.async.wait_group 0;" ::: "memory")
#define CP_WAIT1()  asm volatile("cp.async.wait_group 1;" ::: "memory")

// ---------------------------------------------------------------------------
// TF32 GEMM v2: 128x128 tile, BK=32, cp.async 2-stage double buffer.
// Raw fp32 in smem; cvt.rn.tf32 at fragment load (numerics identical to v1).
// 8 warps (2x4), warp tile 64x32. Conflict-free strides:
//   As[m][k] stride 36: frag banks 36m+k mod 32 = 4m+k distinct
//   Bs[k][n] stride 136: frag banks 8k+n distinct
// ---------------------------------------------------------------------------
#define AST2 36
#define BST2 136
#define A_STG (128 * AST2 * 4)            // 18432 B
#define B_STG (32 * BST2 * 4)             // 17408 B
#define STG2  (A_STG + B_STG)             // 35840 B
#define GEMM_SMEM (2 * STG2)              // 71680 B

__global__ void __launch_bounds__(256, 2) tf32_gemm_kernel(
    const float* __restrict__ A, const float* __restrict__ B,
    const float* __restrict__ bias, float* __restrict__ C,
    int M, int N, int K)
{
    extern __shared__ float smemg[];
    const uint32_t sb = s2u(smemg);

    const int tid  = threadIdx.x;
    const int lane = tid & 31;
    const int warp = tid >> 5;
    const int m0 = blockIdx.y * 128;
    const int n0 = blockIdx.x * 128;

    const int wrow = warp >> 2;
    const int wcol = warp & 3;
    const int mbase = wrow * 64;
    const int nbase = wcol * 32;
    const int r = lane >> 2;
    const int c = lane & 3;

    const float* Ab = A + (size_t)m0 * K;
    const float* Bb = B + n0;

    // loader indices: A 128 rows x 32 cols (2 thr/row, 4 cp16 each)
    const int ar = tid >> 1;
    const int ac = (tid & 1) * 16;         // float offset of first cp16
    // B 32 rows x 128 cols (8 thr/row, 4 cp16 each)
    const int br = tid >> 3;
    const int bc = (tid & 7) * 16;

    auto load_chunk = [&](int kc, int buf) {
        const uint32_t ba = sb + buf * STG2;
        const uint32_t bbs = ba + A_STG;
        const float* asrc = Ab + (size_t)ar * K + kc * 32;
        #pragma unroll
        for (int q = 0; q < 4; q++)
            cpasync16(ba + (ar * AST2 + ac + q * 4) * 4, asrc + ac + q * 4);
        const float* bsrc = Bb + (size_t)(kc * 32 + br) * N;
        #pragma unroll
        for (int q = 0; q < 4; q++)
            cpasync16(bbs + (br * BST2 + bc + q * 4) * 4, bsrc + bc + q * 4);
        CP_COMMIT();
    };

    float acc[4][4][4];
    #pragma unroll
    for (int i = 0; i < 4; i++)
        #pragma unroll
        for (int j = 0; j < 4; j++)
            #pragma unroll
            for (int t = 0; t < 4; t++) acc[i][j][t] = 0.f;

    const int NCH = K / 32;
    load_chunk(0, 0);
    if (NCH > 1) load_chunk(1, 1);

    for (int i = 0; i < NCH; i++) {
        const int buf = i & 1;
        if (i + 1 < NCH) { CP_WAIT1(); } else { CP_WAIT0(); }
        __syncthreads();

        const float* As = smemg + buf * (STG2 / 4);
        const float* Bs = As + (A_STG / 4);

        #pragma unroll
        for (int ks = 0; ks < 4; ks++) {
            const int kb = ks * 8;
            uint32_t af[4][4];
            #pragma unroll
            for (int mt = 0; mt < 4; mt++) {
                const int m = mbase + mt * 16;
                af[mt][0] = tf32u(As[(m + r) * AST2 + kb + c]);
                af[mt][1] = tf32u(As[(m + r + 8) * AST2 + kb + c]);
                af[mt][2] = tf32u(As[(m + r) * AST2 + kb + c + 4]);
                af[mt][3] = tf32u(As[(m + r + 8) * AST2 + kb + c + 4]);
            }
            uint32_t bf[4][2];
            #pragma unroll
            for (int nt = 0; nt < 4; nt++) {
                const int n = nbase + nt * 8 + r;
                bf[nt][0] = tf32u(Bs[(kb + c) * BST2 + n]);
                bf[nt][1] = tf32u(Bs[(kb + c + 4) * BST2 + n]);
            }
            #pragma unroll
            for (int mt = 0; mt < 4; mt++)
                #pragma unroll
                for (int nt = 0; nt < 4; nt++)
                    mma_tf32(acc[mt][nt][0], acc[mt][nt][1],
                             acc[mt][nt][2], acc[mt][nt][3],
                             af[mt][0], af[mt][1], af[mt][2], af[mt][3],
                             bf[nt][0], bf[nt][1]);
        }
        __syncthreads();
        if (i + 2 < NCH) load_chunk(i + 2, buf);
    }

    #pragma unroll
    for (int mt = 0; mt < 4; mt++) {
        const int row0 = m0 + mbase + mt * 16 + r;
        #pragma unroll
        for (int nt = 0; nt < 4; nt++) {
            const int col = n0 + nbase + nt * 8 + 2 * c;
            float2 v0 = make_float2(acc[mt][nt][0], acc[mt][nt][1]);
            float2 v1 = make_float2(acc[mt][nt][2], acc[mt][nt][3]);
            if (bias) {
                float2 bb = *(const float2*)(bias + col);
                v0.x += bb.x; v0.y += bb.y;
                v1.x += bb.x; v1.y += bb.y;
            }
            *(float2*)(C + (size_t)row0 * N + col)       = v0;
            *(float2*)(C + (size_t)(row0 + 8) * N + col) = v1;
        }
    }
}

// ---------------------------------------------------------------------------
// Flash attention v3 (tf32 mma), causal. vs round 6:
//  - Q stored raw fp32 once; hi/lo recomputed at fragment load (same values)
//  - K/V double-buffered: next tile's cp.async overlaps current compute
// smem = 34816 + 2*(17408+18432) = 106496 B -> still 2 CTAs/SM.
// ---------------------------------------------------------------------------
#define FBM 128
#define FBN 64
#define QST 68
#define KST 68
#define VST 72
#define KV_STG ((FBN*KST + FBN*VST) * 4)                  // 35840 B
#define FLASH_SMEM (FBM*QST*4 + 2*KV_STG)                 // 106496 B

__global__ void __launch_bounds__(256, 2) flash_tc_kernel(
    const float* __restrict__ qkv, float* __restrict__ out)
{
    extern __shared__ float sm[];
    float* Qs  = sm;                       // [128][QST] raw fp32
    float* KV0 = Qs + FBM * QST;           // stage 0: Ks then Vs

    const int tid  = threadIdx.x;
    const int lane = tid & 31;
    const int warp = tid >> 5;
    const int qt = (int)gridDim.x - 1 - (int)blockIdx.x;   // big blocks first
    const int bh = blockIdx.y;
    const int b  = bh >> 4;
    const int h  = bh & 15;

    const size_t rs = (size_t)QKV_N;
    const float* qb = qkv + (size_t)b * SEQ * rs + h * HD;
    const float* kb = qb + DMODEL;
    const int q0 = qt * FBM;

    // Q prologue: raw fp32
    for (int idx = tid; idx < FBM * 16; idx += 256) {
        int rr = idx >> 4, c4 = (idx & 15) * 4;
        *(float4*)&Qs[rr * QST + c4] = *(const float4*)(qb + (size_t)(q0 + rr) * rs + c4);
    }

    auto load_kv = [&](int kt, int buf) {
        float* Ks = KV0 + buf * (KV_STG / 4);
        float* Vs = Ks + FBN * KST;
        for (int idx = tid; idx < FBN * 16; idx += 256) {
            int rr = idx >> 4, ch = (idx & 15) * 4;
            const float* src = kb + (size_t)(kt * FBN + rr) * rs + ch;
            cpasync16(s2u(&Ks[rr * KST + ch]), src);
            cpasync16(s2u(&Vs[rr * VST + ch]), src + DMODEL);
        }
        CP_COMMIT();
    };

    const int r = lane >> 2;
    const int c = lane & 3;
    const int m0 = warp * 16;

    float o[8][4];
    #pragma unroll
    for (int nt = 0; nt < 8; nt++)
        #pragma unroll
        for (int t = 0; t < 4; t++) o[nt][t] = 0.f;
    float mx0 = -1e30f, mx1 = -1e30f, l0 = 0.f, l1 = 0.f;
    const float sl2e = 0.125f * 1.4426950408889634f;

    const int nkt = 2 * qt + 2;
    load_kv(0, 0);

    for (int kt = 0; kt < nkt; kt++) {
        const int buf = kt & 1;
        if (kt + 1 < nkt) { load_kv(kt + 1, 1 - buf); CP_WAIT1(); }
        else              { CP_WAIT0(); }
        __syncthreads();   // stage ready; also covers Q stores (iter 0) and
                           // previous compute on the buffer being loaded next

        const float* Ks = KV0 + buf * (KV_STG / 4);
        const float* Vs = Ks + FBN * KST;

        // ---- S = Q @ K^T, Qhi+Qlo split computed in-register ----
        float s[8][4];
        #pragma unroll
        for (int nt = 0; nt < 8; nt++)
            #pragma unroll
            for (int t = 0; t < 4; t++) s[nt][t] = 0.f;

        #pragma unroll
        for (int kc = 0; kc < 8; kc++) {
            const int k8 = kc * 8;
            float q00 = Qs[(m0 + r) * QST + k8 + c];
            float q10 = Qs[(m0 + r + 8) * QST + k8 + c];
            float q01 = Qs[(m0 + r) * QST + k8 + c + 4];
            float q11 = Qs[(m0 + r + 8) * QST + k8 + c + 4];
            float h00 = tf32f(q00), h10 = tf32f(q10), h01 = tf32f(q01), h11 = tf32f(q11);
            uint32_t ah0 = __float_as_uint(h00), ah1 = __float_as_uint(h10);
            uint32_t ah2 = __float_as_uint(h01), ah3 = __float_as_uint(h11);
            uint32_t al0 = tf32u(q00 - h00), al1 = tf32u(q10 - h10);
            uint32_t al2 = tf32u(q01 - h01), al3 = tf32u(q11 - h11);
            #pragma unroll
            for (int nt = 0; nt < 8; nt++) {
                uint32_t b0 = tf32u(Ks[(nt * 8 + r) * KST + k8 + c]);
                uint32_t b1 = tf32u(Ks[(nt * 8 + r) * KST + k8 + c + 4]);
                mma_tf32(s[nt][0], s[nt][1], s[nt][2], s[nt][3], ah0, ah1, ah2, ah3, b0, b1);
                mma_tf32(s[nt][0], s[nt][1], s[nt][2], s[nt][3], al0, al1, al2, al3, b0, b1);
            }
        }

        // ---- causal mask ----
        if (kt >= 2 * qt) {
            const int q0i = q0 + m0 + r;
            #pragma unroll
            for (int nt = 0; nt < 8; nt++) {
                int k0i = kt * FBN + nt * 8 + 2 * c;
                if (k0i     > q0i)     s[nt][0] = -1e30f;
                if (k0i + 1 > q0i)     s[nt][1] = -1e30f;
                if (k0i     > q0i + 8) s[nt][2] = -1e30f;
                if (k0i + 1 > q0i + 8) s[nt][3] = -1e30f;
            }
        }

        // ---- online softmax: row r ----
        {
            float t = -1e30f;
            #pragma unroll
            for (int nt = 0; nt < 8; nt++) t = fmaxf(t, fmaxf(s[nt][0], s[nt][1]));
            t = fmaxf(t, __shfl_xor_sync(0xffffffffu, t, 1));
            t = fmaxf(t, __shfl_xor_sync(0xffffffffu, t, 2));
            t *= sl2e;
            float mn = fmaxf(mx0, t);
            float alpha = exp2f(mx0 - mn);
            float ps = 0.f;
            #pragma unroll
            for (int nt = 0; nt < 8; nt++) {
                float p0 = exp2f(s[nt][0] * sl2e - mn);
                float p1 = exp2f(s[nt][1] * sl2e - mn);
                s[nt][0] = p0; s[nt][1] = p1; ps += p0 + p1;
            }
            ps += __shfl_xor_sync(0xffffffffu, ps, 1);
            ps += __shfl_xor_sync(0xffffffffu, ps, 2);
            l0 = l0 * alpha + ps; mx0 = mn;
            #pragma unroll
            for (int nt = 0; nt < 8; nt++) { o[nt][0] *= alpha; o[nt][1] *= alpha; }
        }
        // ---- row r+8 ----
        {
            float t = -1e30f;
            #pragma unroll
            for (int nt = 0; nt < 8; nt++) t = fmaxf(t, fmaxf(s[nt][2], s[nt][3]));
            t = fmaxf(t, __shfl_xor_sync(0xffffffffu, t, 1));
            t = fmaxf(t, __shfl_xor_sync(0xffffffffu, t, 2));
            t *= sl2e;
            float mn = fmaxf(mx1, t);
            float alpha = exp2f(mx1 - mn);
            float ps = 0.f;
            #pragma unroll
            for (int nt = 0; nt < 8; nt++) {
                float p0 = exp2f(s[nt][2] * sl2e - mn);
                float p1 = exp2f(s[nt][3] * sl2e - mn);
                s[nt][2] = p0; s[nt][3] = p1; ps += p0 + p1;
            }
            ps += __shfl_xor_sync(0xffffffffu, ps, 1);
            ps += __shfl_xor_sync(0xffffffffu, ps, 2);
            l1 = l1 * alpha + ps; mx1 = mn;
            #pragma unroll
            for (int nt = 0; nt < 8; nt++) { o[nt][2] *= alpha; o[nt][3] *= alpha; }
        }

        // ---- O += P @ V : P relayout via shuffles ----
        {
            const int src0 = 4 * r + (c >> 1);
            const int src1 = src0 + 2;
            const bool odd = (c & 1);
            #pragma unroll
            for (int kc = 0; kc < 8; kc++) {
                const int k8 = kc * 8;
                float t00 = __shfl_sync(0xffffffffu, s[kc][0], src0);
                float t01 = __shfl_sync(0xffffffffu, s[kc][1], src0);
                float t02 = __shfl_sync(0xffffffffu, s[kc][2], src0);
                float t03 = __shfl_sync(0xffffffffu, s[kc][3], src0);
                float t10 = __shfl_sync(0xffffffffu, s[kc][0], src1);
                float t11 = __shfl_sync(0xffffffffu, s[kc][1], src1);
                float t12 = __shfl_sync(0xffffffffu, s[kc][2], src1);
                float t13 = __shfl_sync(0xffffffffu, s[kc][3], src1);
                uint32_t a0 = tf32u(odd ? t01 : t00);
                uint32_t a1 = tf32u(odd ? t03 : t02);
                uint32_t a2 = tf32u(odd ? t11 : t10);
                uint32_t a3 = tf32u(odd ? t13 : t12);
                #pragma unroll
                for (int nt = 0; nt < 8; nt++) {
                    uint32_t b0 = tf32u(Vs[(k8 + c) * VST + nt * 8 + r]);
                    uint32_t b1 = tf32u(Vs[(k8 + c + 4) * VST + nt * 8 + r]);
                    mma_tf32(o[nt][0], o[nt][1], o[nt][2], o[nt][3], a0, a1, a2, a3, b0, b1);
                }
            }
        }
        __syncthreads();   // compute done before this buffer is reloaded
    }

    // ---- epilogue ----
    const float inv0 = 1.f / l0;
    const float inv1 = 1.f / l1;
    const size_t row0 = (size_t)(b * SEQ + q0 + m0 + r) * DMODEL + h * HD;
    const size_t row1 = row0 + (size_t)8 * DMODEL;
    #pragma unroll
    for (int nt = 0; nt < 8; nt++) {
        const int col = nt * 8 + 2 * c;
        *(float2*)(out + row0 + col) = make_float2(o[nt][0] * inv0, o[nt][1] * inv0);
        *(float2*)(out + row1 + col) = make_float2(o[nt][2] * inv1, o[nt][3] * inv1);
    }
}

// ---------------------------------------------------------------------------
extern "C" void kernel_launch(void* const* d_in, const int* in_sizes, int n_in,
                              void* d_out, int out_size)
{
    const float* x     = (const float*)d_in[0];
    const float* w_qkv = (const float*)d_in[1];
    const float* w_out = (const float*)d_in[2];
    const float* b_out = (const float*)d_in[3];
    float* out = (float*)d_out;

    float *qkv, *att;
    cudaGetSymbolAddress((void**)&qkv, g_qkv);
    cudaGetSymbolAddress((void**)&att, g_att);

    cudaFuncSetAttribute(tf32_gemm_kernel,
                         cudaFuncAttributeMaxDynamicSharedMemorySize, GEMM_SMEM);
    cudaFuncSetAttribute(flash_tc_kernel,
                         cudaFuncAttributeMaxDynamicSharedMemorySize, FLASH_SMEM);

    // 1) QKV projection (tf32 mma, cp.async double buffer)
    {
        dim3 grid(QKV_N / 128, ROWS / 128);
        tf32_gemm_kernel<<<grid, 256, GEMM_SMEM>>>(x, w_qkv, nullptr, qkv,
                                                   ROWS, QKV_N, DMODEL);
    }

    // 2) Flash attention v3 (tf32 mma, double-buffered K/V, 2 CTAs/SM)
    {
        dim3 grid(SEQ / FBM, BATCH * NHEADS);
        flash_tc_kernel<<<grid, 256, FLASH_SMEM>>>(qkv, att);
    }

    // 3) Output projection + bias
    {
        dim3 grid(DMODEL / 128, ROWS / 128);
        tf32_gemm_kernel<<<grid, 256, GEMM_SMEM>>>(att, w_out, b_out, out,
                                                   ROWS, DMODEL, DMODEL);
    }
}

// round 9
// speedup vs baseline: 1.2487x; 1.2125x over previous
#include <cuda_runtime.h>
#include <cuda_bf16.h>
#include <cstdint>

// Problem constants
#define BATCH 4
#define SEQ   2048
#define DMODEL 1024
#define NHEADS 16
#define HD    64
#define ROWS  (BATCH * SEQ)          // 8192
#define QKV_N (3 * DMODEL)           // 3072

// Scratch (allocation-free rule: __device__ globals)
__device__ float g_qkv[(size_t)ROWS * QKV_N];
__device__ float g_att[(size_t)ROWS * DMODEL];

// ---------------------------------------------------------------------------
// helpers
// ---------------------------------------------------------------------------
__device__ __forceinline__ uint32_t s2u(const void* p) {
    uint32_t a;
    asm("{ .reg .u64 t; cvta.to.shared.u64 t, %1; cvt.u32.u64 %0, t; }"
        : "=r"(a) : "l"(p));
    return a;
}
__device__ __forceinline__ uint32_t tf32u(float x) {
    uint32_t u; asm("cvt.rn.tf32.f32 %0, %1;" : "=r"(u) : "f"(x)); return u;
}
__device__ __forceinline__ float tf32f(float x) { return __uint_as_float(tf32u(x)); }

__device__ __forceinline__ void mma_tf32(float& d0, float& d1, float& d2, float& d3,
                                         uint32_t a0, uint32_t a1, uint32_t a2, uint32_t a3,
                                         uint32_t b0, uint32_t b1)
{
    asm volatile(
        "mma.sync.aligned.m16n8k8.row.col.f32.tf32.tf32.f32 "
        "{%0,%1,%2,%3}, {%4,%5,%6,%7}, {%8,%9}, {%0,%1,%2,%3};"
        : "+f"(d0), "+f"(d1), "+f"(d2), "+f"(d3)
        : "r"(a0), "r"(a1), "r"(a2), "r"(a3), "r"(b0), "r"(b1));
}

__device__ __forceinline__ void mma_bf16(float& d0, float& d1, float& d2, float& d3,
                                         uint32_t a0, uint32_t a1, uint32_t a2, uint32_t a3,
                                         uint32_t b0, uint32_t b1)
{
    asm volatile(
        "mma.sync.aligned.m16n8k16.row.col.f32.bf16.bf16.f32 "
        "{%0,%1,%2,%3}, {%4,%5,%6,%7}, {%8,%9}, {%0,%1,%2,%3};"
        : "+f"(d0), "+f"(d1), "+f"(d2), "+f"(d3)
        : "r"(a0), "r"(a1), "r"(a2), "r"(a3), "r"(b0), "r"(b1));
}

__device__ __forceinline__ void cpasync16(uint32_t dst, const void* src) {
    asm volatile("cp.async.cg.shared.global [%0], [%1], 16;" :: "r"(dst), "l"(src));
}
#define CP_COMMIT() asm volatile("cp.async.commit_group;" ::: "memory")
#define CP_WAIT0()  asm volatile("cp.async.wait_group 0;" ::: "memory")

// pack two floats -> bf16x2 (lo = a in bits [15:0], hi = b) + lows
__device__ __forceinline__ uint32_t bfpack(float a, float b) {
    __nv_bfloat162 h = __floats2bfloat162_rn(a, b);
    return *reinterpret_cast<uint32_t*>(&h);
}
__device__ __forceinline__ float bflo(uint32_t u) {   // float of low bf16
    return __uint_as_float(u << 16);
}
__device__ __forceinline__ float bfhi(uint32_t u) {   // float of high bf16
    return __uint_as_float(u & 0xFFFF0000u);
}

// ---------------------------------------------------------------------------
// TF32 GEMM — exact round-2/3/6 kernel (419us QKV, known good; do not touch)
// ---------------------------------------------------------------------------
#define BM 128
#define BN 128
#define BKK 16
#define AST 20
#define BST 136

__global__ void __launch_bounds__(256, 2) tf32_gemm_kernel(
    const float* __restrict__ A, const float* __restrict__ B,
    const float* __restrict__ bias, float* __restrict__ C,
    int M, int N, int K)
{
    __shared__ float As[BM][AST];
    __shared__ float Bs[BKK][BST];

    const int tid  = threadIdx.x;
    const int lane = tid & 31;
    const int warp = tid >> 5;
    const int brow = blockIdx.y;
    const int bcol = blockIdx.x;

    const int am0 = tid >> 2;
    const int aq  = (tid & 3) * 4;
    const int bk0 = tid >> 5;
    const int bn0 = (tid & 31) * 4;

    const int wrow = warp >> 2;
    const int wcol = warp & 3;
    const int mbase = wrow * 64;
    const int nbase = wcol * 32;
    const int r = lane >> 2;
    const int c = lane & 3;

    const float* Ab = A + (size_t)brow * BM * K;
    const float* Bb = B + (size_t)bcol * BN;

    float acc[4][4][4];
    #pragma unroll
    for (int i = 0; i < 4; i++)
        #pragma unroll
        for (int j = 0; j < 4; j++)
            #pragma unroll
            for (int t = 0; t < 4; t++) acc[i][j][t] = 0.f;

    float4 pa0 = *(const float4*)(Ab + (size_t)am0 * K + aq);
    float4 pa1 = *(const float4*)(Ab + (size_t)(am0 + 64) * K + aq);
    float4 pb0 = *(const float4*)(Bb + (size_t)bk0 * N + bn0);
    float4 pb1 = *(const float4*)(Bb + (size_t)(bk0 + 8) * N + bn0);

    for (int k0 = 0; k0 < K; k0 += BKK) {
        *(float4*)&As[am0][aq] = make_float4(tf32f(pa0.x), tf32f(pa0.y), tf32f(pa0.z), tf32f(pa0.w));
        *(float4*)&As[am0 + 64][aq] = make_float4(tf32f(pa1.x), tf32f(pa1.y), tf32f(pa1.z), tf32f(pa1.w));
        *(float4*)&Bs[bk0][bn0] = make_float4(tf32f(pb0.x), tf32f(pb0.y), tf32f(pb0.z), tf32f(pb0.w));
        *(float4*)&Bs[bk0 + 8][bn0] = make_float4(tf32f(pb1.x), tf32f(pb1.y), tf32f(pb1.z), tf32f(pb1.w));
        __syncthreads();

        if (k0 + BKK < K) {
            pa0 = *(const float4*)(Ab + (size_t)am0 * K + k0 + BKK + aq);
            pa1 = *(const float4*)(Ab + (size_t)(am0 + 64) * K + k0 + BKK + aq);
            pb0 = *(const float4*)(Bb + (size_t)(k0 + BKK + bk0) * N + bn0);
            pb1 = *(const float4*)(Bb + (size_t)(k0 + BKK + bk0 + 8) * N + bn0);
        }

        #pragma unroll
        for (int ks = 0; ks < 2; ks++) {
            const int kb = ks * 8;
            uint32_t af[4][4];
            #pragma unroll
            for (int mt = 0; mt < 4; mt++) {
                const int m = mbase + mt * 16;
                af[mt][0] = __float_as_uint(As[m + r][kb + c]);
                af[mt][1] = __float_as_uint(As[m + r + 8][kb + c]);
                af[mt][2] = __float_as_uint(As[m + r][kb + c + 4]);
                af[mt][3] = __float_as_uint(As[m + r + 8][kb + c + 4]);
            }
            uint32_t bf[4][2];
            #pragma unroll
            for (int nt = 0; nt < 4; nt++) {
                const int n = nbase + nt * 8 + r;
                bf[nt][0] = __float_as_uint(Bs[kb + c][n]);
                bf[nt][1] = __float_as_uint(Bs[kb + c + 4][n]);
            }
            #pragma unroll
            for (int mt = 0; mt < 4; mt++)
                #pragma unroll
                for (int nt = 0; nt < 4; nt++)
                    mma_tf32(acc[mt][nt][0], acc[mt][nt][1],
                             acc[mt][nt][2], acc[mt][nt][3],
                             af[mt][0], af[mt][1], af[mt][2], af[mt][3],
                             bf[nt][0], bf[nt][1]);
        }
        __syncthreads();
    }

    #pragma unroll
    for (int mt = 0; mt < 4; mt++) {
        const int row0 = brow * BM + mbase + mt * 16 + r;
        #pragma unroll
        for (int nt = 0; nt < 4; nt++) {
            const int col = bcol * BN + nbase + nt * 8 + 2 * c;
            float2 v0 = make_float2(acc[mt][nt][0], acc[mt][nt][1]);
            float2 v1 = make_float2(acc[mt][nt][2], acc[mt][nt][3]);
            if (bias) {
                float2 bb = *(const float2*)(bias + col);
                v0.x += bb.x; v0.y += bb.y;
                v1.x += bb.x; v1.y += bb.y;
            }
            *(float2*)(C + (size_t)row0 * N + col)       = v0;
            *(float2*)(C + (size_t)(row0 + 8) * N + col) = v1;
        }
    }
}

// ---------------------------------------------------------------------------
// Flash attention v4, causal. vs round 6:
//  S-phase: bf16 3-split mma.m16n8k16 (QhKh + QhKl + QlKh), 3 instr/k16 vs 4.
//  Q split+packed bf16x2 once in prologue; K split+packed by the tile loader.
//  PV unchanged: tf32 single, shuffle P-relayout, raw fp32 V.
// smem: Qh/Ql 2*18432 + Kh/Kl 2*9216 + V 18432 = 73728 B -> 2 CTAs/SM.
// ---------------------------------------------------------------------------
#define FBM 128
#define FBN 64
#define QBST 36   // packed regs per Q row (32 data + 4 pad) -> banks 4r+c
#define KBST 36
#define VST 72
#define FLASH_SMEM ((2*FBM*QBST + 2*FBN*KBST + FBN*VST) * 4)   // 73728 B

__global__ void __launch_bounds__(256, 2) flash_tc_kernel(
    const float* __restrict__ qkv, float* __restrict__ out)
{
    extern __shared__ uint32_t smf[];
    uint32_t* Qh = smf;
    uint32_t* Ql = Qh + FBM * QBST;
    uint32_t* Kh = Ql + FBM * QBST;
    uint32_t* Kl = Kh + FBN * KBST;
    float*    Vs = (float*)(Kl + FBN * KBST);

    const int tid  = threadIdx.x;
    const int lane = tid & 31;
    const int warp = tid >> 5;
    const int qt = (int)gridDim.x - 1 - (int)blockIdx.x;   // big blocks first
    const int bh = blockIdx.y;
    const int b  = bh >> 4;
    const int h  = bh & 15;

    const size_t rs = (size_t)QKV_N;
    const float* qb = qkv + (size_t)b * SEQ * rs + h * HD;
    const float* kb = qb + DMODEL;
    const int q0 = qt * FBM;

    // ---- Q prologue: load fp32, split to bf16 hi/lo, pack pairs ----
    for (int idx = tid; idx < FBM * 32; idx += 256) {
        const int row = idx >> 5, j = idx & 31;
        float2 q = *(const float2*)(qb + (size_t)(q0 + row) * rs + 2 * j);
        uint32_t hu = bfpack(q.x, q.y);
        Qh[row * QBST + j] = hu;
        Ql[row * QBST + j] = bfpack(q.x - bflo(hu), q.y - bfhi(hu));
    }

    const int r = lane >> 2;       // 0..7
    const int c = lane & 3;        // 0..3
    const int m0 = warp * 16;

    float o[8][4];
    #pragma unroll
    for (int nt = 0; nt < 8; nt++)
        #pragma unroll
        for (int t = 0; t < 4; t++) o[nt][t] = 0.f;
    float mx0 = -1e30f, mx1 = -1e30f, l0 = 0.f, l1 = 0.f;
    const float sl2e = 0.125f * 1.4426950408889634f;

    const int nkt = 2 * qt + 2;
    for (int kt = 0; kt < nkt; kt++) {
        __syncthreads();   // previous iter's readers done (covers Q stores iter 0)

        // V tile: raw fp32 via cp.async
        for (int idx = tid; idx < FBN * 16; idx += 256) {
            int rr = idx >> 4, ch = (idx & 15) * 4;
            cpasync16(s2u(&Vs[rr * VST + ch]),
                      kb + (size_t)(kt * FBN + rr) * rs + DMODEL + ch);
        }
        CP_COMMIT();
        // K tile: LDG.64 + split + packed STS (each element converted once)
        for (int idx = tid; idx < FBN * 32; idx += 256) {
            const int row = idx >> 5, j = idx & 31;
            float2 kv = *(const float2*)(kb + (size_t)(kt * FBN + row) * rs + 2 * j);
            uint32_t hu = bfpack(kv.x, kv.y);
            Kh[row * KBST + j] = hu;
            Kl[row * KBST + j] = bfpack(kv.x - bflo(hu), kv.y - bfhi(hu));
        }
        CP_WAIT0();
        __syncthreads();

        // ---- S = Q @ K^T : bf16 3-split, 3 mma.k16 per (g, nt) ----
        float s[8][4];
        #pragma unroll
        for (int nt = 0; nt < 8; nt++)
            #pragma unroll
            for (int t = 0; t < 4; t++) s[nt][t] = 0.f;

        #pragma unroll
        for (int g = 0; g < 4; g++) {
            const int qo = 8 * g + c;
            uint32_t ah0 = Qh[(m0 + r) * QBST + qo];
            uint32_t ah1 = Qh[(m0 + r + 8) * QBST + qo];
            uint32_t ah2 = Qh[(m0 + r) * QBST + qo + 4];
            uint32_t ah3 = Qh[(m0 + r + 8) * QBST + qo + 4];
            uint32_t al0 = Ql[(m0 + r) * QBST + qo];
            uint32_t al1 = Ql[(m0 + r + 8) * QBST + qo];
            uint32_t al2 = Ql[(m0 + r) * QBST + qo + 4];
            uint32_t al3 = Ql[(m0 + r + 8) * QBST + qo + 4];
            #pragma unroll
            for (int half = 0; half < 2; half++) {
                uint32_t bhf[4][2], blf[4][2];
                #pragma unroll
                for (int q2 = 0; q2 < 4; q2++) {
                    const int n = (half * 4 + q2) * 8 + r;
                    bhf[q2][0] = Kh[n * KBST + qo];
                    bhf[q2][1] = Kh[n * KBST + qo + 4];
                    blf[q2][0] = Kl[n * KBST + qo];
                    blf[q2][1] = Kl[n * KBST + qo + 4];
                }
                #pragma unroll
                for (int q2 = 0; q2 < 4; q2++) {
                    const int nt = half * 4 + q2;
                    mma_bf16(s[nt][0], s[nt][1], s[nt][2], s[nt][3],
                             ah0, ah1, ah2, ah3, bhf[q2][0], bhf[q2][1]);
                }
                #pragma unroll
                for (int q2 = 0; q2 < 4; q2++) {
                    const int nt = half * 4 + q2;
                    mma_bf16(s[nt][0], s[nt][1], s[nt][2], s[nt][3],
                             ah0, ah1, ah2, ah3, blf[q2][0], blf[q2][1]);
                }
                #pragma unroll
                for (int q2 = 0; q2 < 4; q2++) {
                    const int nt = half * 4 + q2;
                    mma_bf16(s[nt][0], s[nt][1], s[nt][2], s[nt][3],
                             al0, al1, al2, al3, bhf[q2][0], bhf[q2][1]);
                }
            }
        }

        // ---- causal mask ----
        if (kt >= 2 * qt) {
            const int q0i = q0 + m0 + r;
            #pragma unroll
            for (int nt = 0; nt < 8; nt++) {
                int k0i = kt * FBN + nt * 8 + 2 * c;
                if (k0i     > q0i)     s[nt][0] = -1e30f;
                if (k0i + 1 > q0i)     s[nt][1] = -1e30f;
                if (k0i     > q0i + 8) s[nt][2] = -1e30f;
                if (k0i + 1 > q0i + 8) s[nt][3] = -1e30f;
            }
        }

        // ---- online softmax: row r ----
        {
            float t = -1e30f;
            #pragma unroll
            for (int nt = 0; nt < 8; nt++) t = fmaxf(t, fmaxf(s[nt][0], s[nt][1]));
            t = fmaxf(t, __shfl_xor_sync(0xffffffffu, t, 1));
            t = fmaxf(t, __shfl_xor_sync(0xffffffffu, t, 2));
            t *= sl2e;
            float mn = fmaxf(mx0, t);
            float alpha = exp2f(mx0 - mn);
            float ps = 0.f;
            #pragma unroll
            for (int nt = 0; nt < 8; nt++) {
                float p0 = exp2f(s[nt][0] * sl2e - mn);
                float p1 = exp2f(s[nt][1] * sl2e - mn);
                s[nt][0] = p0; s[nt][1] = p1; ps += p0 + p1;
            }
            ps += __shfl_xor_sync(0xffffffffu, ps, 1);
            ps += __shfl_xor_sync(0xffffffffu, ps, 2);
            l0 = l0 * alpha + ps; mx0 = mn;
            #pragma unroll
            for (int nt = 0; nt < 8; nt++) { o[nt][0] *= alpha; o[nt][1] *= alpha; }
        }
        // ---- row r+8 ----
        {
            float t = -1e30f;
            #pragma unroll
            for (int nt = 0; nt < 8; nt++) t = fmaxf(t, fmaxf(s[nt][2], s[nt][3]));
            t = fmaxf(t, __shfl_xor_sync(0xffffffffu, t, 1));
            t = fmaxf(t, __shfl_xor_sync(0xffffffffu, t, 2));
            t *= sl2e;
            float mn = fmaxf(mx1, t);
            float alpha = exp2f(mx1 - mn);
            float ps = 0.f;
            #pragma unroll
            for (int nt = 0; nt < 8; nt++) {
                float p0 = exp2f(s[nt][2] * sl2e - mn);
                float p1 = exp2f(s[nt][3] * sl2e - mn);
                s[nt][2] = p0; s[nt][3] = p1; ps += p0 + p1;
            }
            ps += __shfl_xor_sync(0xffffffffu, ps, 1);
            ps += __shfl_xor_sync(0xffffffffu, ps, 2);
            l1 = l1 * alpha + ps; mx1 = mn;
            #pragma unroll
            for (int nt = 0; nt < 8; nt++) { o[nt][2] *= alpha; o[nt][3] *= alpha; }
        }

        // ---- O += P @ V : tf32, P relayout via shuffles (round-6 path) ----
        {
            const int src0 = 4 * r + (c >> 1);
            const int src1 = src0 + 2;
            const bool odd = (c & 1);
            #pragma unroll
            for (int kc = 0; kc < 8; kc++) {
                const int k8 = kc * 8;
                float t00 = __shfl_sync(0xffffffffu, s[kc][0], src0);
                float t01 = __shfl_sync(0xffffffffu, s[kc][1], src0);
                float t02 = __shfl_sync(0xffffffffu, s[kc][2], src0);
                float t03 = __shfl_sync(0xffffffffu, s[kc][3], src0);
                float t10 = __shfl_sync(0xffffffffu, s[kc][0], src1);
                float t11 = __shfl_sync(0xffffffffu, s[kc][1], src1);
                float t12 = __shfl_sync(0xffffffffu, s[kc][2], src1);
                float t13 = __shfl_sync(0xffffffffu, s[kc][3], src1);
                uint32_t a0 = tf32u(odd ? t01 : t00);
                uint32_t a1 = tf32u(odd ? t03 : t02);
                uint32_t a2 = tf32u(odd ? t11 : t10);
                uint32_t a3 = tf32u(odd ? t13 : t12);
                #pragma unroll
                for (int nt = 0; nt < 8; nt++) {
                    uint32_t b0 = tf32u(Vs[(k8 + c) * VST + nt * 8 + r]);
                    uint32_t b1 = tf32u(Vs[(k8 + c + 4) * VST + nt * 8 + r]);
                    mma_tf32(o[nt][0], o[nt][1], o[nt][2], o[nt][3], a0, a1, a2, a3, b0, b1);
                }
            }
        }
    }

    // ---- epilogue ----
    const float inv0 = 1.f / l0;
    const float inv1 = 1.f / l1;
    const size_t row0 = (size_t)(b * SEQ + q0 + m0 + r) * DMODEL + h * HD;
    const size_t row1 = row0 + (size_t)8 * DMODEL;
    #pragma unroll
    for (int nt = 0; nt < 8; nt++) {
        const int col = nt * 8 + 2 * c;
        *(float2*)(out + row0 + col) = make_float2(o[nt][0] * inv0, o[nt][1] * inv0);
        *(float2*)(out + row1 + col) = make_float2(o[nt][2] * inv1, o[nt][3] * inv1);
    }
}

// ---------------------------------------------------------------------------
extern "C" void kernel_launch(void* const* d_in, const int* in_sizes, int n_in,
                              void* d_out, int out_size)
{
    const float* x     = (const float*)d_in[0];
    const float* w_qkv = (const float*)d_in[1];
    const float* w_out = (const float*)d_in[2];
    const float* b_out = (const float*)d_in[3];
    float* out = (float*)d_out;

    float *qkv, *att;
    cudaGetSymbolAddress((void**)&qkv, g_qkv);
    cudaGetSymbolAddress((void**)&att, g_att);

    // 1) QKV projection (tf32 mma, round-2 kernel)
    {
        dim3 grid(QKV_N / BN, ROWS / BM);
        tf32_gemm_kernel<<<grid, 256>>>(x, w_qkv, nullptr, qkv, ROWS, QKV_N, DMODEL);
    }

    // 2) Flash attention v4 (bf16 3-split S, tf32 PV, 2 CTAs/SM)
    {
        cudaFuncSetAttribute(flash_tc_kernel,
                             cudaFuncAttributeMaxDynamicSharedMemorySize, FLASH_SMEM);
        dim3 grid(SEQ / FBM, BATCH * NHEADS);
        flash_tc_kernel<<<grid, 256, FLASH_SMEM>>>(qkv, att);
    }

    // 3) Output projection + bias
    {
        dim3 grid(DMODEL / BN, ROWS / BM);
        tf32_gemm_kernel<<<grid, 256>>>(att, w_out, b_out, out, ROWS, DMODEL, DMODEL);
    }
}